// round 7
// baseline (speedup 1.0000x reference)
#include <cuda_runtime.h>
#include <cuda_bf16.h>
#include <math.h>
#include <stdint.h>

#define TT   8192
#define CD   1024
#define FD   1024
#define NE   8
#define HWD  4096
#define BD   2
#define NENT (TT*2)

#define G1_NT 16          // gemm1 n-tiles (FD/64)
#define G2_NT 8           // gemm2 n-tiles (CD/128)
#define MT    136         // max m-tiles
#define G1_CTAS (G1_NT*MT)
#define G2_CTAS (G2_NT*MT)

// ---------------- scratch (16B-aligned for cp.async / vector ld-st) ----------------
__device__ __align__(16) float         g_X  [TT * CD];
__device__ __align__(16) __nv_bfloat16 g_Xh [TT * CD];
__device__ __align__(16) __nv_bfloat16 g_Xl [TT * CD];
__device__ __align__(16) __nv_bfloat16 g_W1h[NE * FD * CD];
__device__ __align__(16) __nv_bfloat16 g_W1l[NE * FD * CD];
__device__ __align__(16) __nv_bfloat16 g_W3h[NE * FD * CD];
__device__ __align__(16) __nv_bfloat16 g_W3l[NE * FD * CD];
__device__ __align__(16) __nv_bfloat16 g_W2h[NE * CD * FD];
__device__ __align__(16) __nv_bfloat16 g_W2l[NE * CD * FD];
__device__ __align__(16) __nv_bfloat16 g_Hh [NENT * FD];
__device__ __align__(16) __nv_bfloat16 g_Hl [NENT * FD];
__device__ __align__(16) float         g_Y  [NENT * CD];
__device__ __align__(16) float         g_wt [NENT];
__device__ int           g_cnt[NE];
__device__ __align__(16) int           g_list[NE * TT];
__device__ __align__(16) int           g_tile_e[160];
__device__ __align__(16) int           g_tile_m0[160];
__device__ int           g_ntiles;
__device__ __align__(16) int           g_done[160];

// ---------------- helpers ----------------
__device__ __forceinline__ uint32_t smem_u32(const void* p) {
    uint32_t a;
    asm("{ .reg .u64 t; cvta.to.shared.u64 t, %1; cvt.u32.u64 %0, t; }" : "=r"(a) : "l"(p));
    return a;
}
__device__ __forceinline__ void cp16(uint32_t dst, const void* src) {
    asm volatile("cp.async.cg.shared.global [%0], [%1], 16;" :: "r"(dst), "l"(src) : "memory");
}
#define CP_COMMIT() asm volatile("cp.async.commit_group;" ::: "memory")
#define CP_WAIT0()  asm volatile("cp.async.wait_group 0;" ::: "memory")

__device__ __forceinline__ void ldsm4(uint32_t* r, uint32_t a) {
    asm volatile("ldmatrix.sync.aligned.m8n8.x4.shared.b16 {%0,%1,%2,%3}, [%4];"
        : "=r"(r[0]), "=r"(r[1]), "=r"(r[2]), "=r"(r[3]) : "r"(a));
}
__device__ __forceinline__ void mma_bf16(float* c, const uint32_t* a, const uint32_t* b) {
    asm volatile(
        "mma.sync.aligned.m16n8k16.row.col.f32.bf16.bf16.f32 "
        "{%0,%1,%2,%3}, {%4,%5,%6,%7}, {%8,%9}, {%0,%1,%2,%3};"
        : "+f"(c[0]), "+f"(c[1]), "+f"(c[2]), "+f"(c[3])
        : "r"(a[0]), "r"(a[1]), "r"(a[2]), "r"(a[3]), "r"(b[0]), "r"(b[1]));
}
__device__ __forceinline__ void split_bf16(float f, __nv_bfloat16& h, __nv_bfloat16& l) {
    h = __float2bfloat16(f);
    l = __float2bfloat16(f - __bfloat162float(h));
}

// smem stage layout (bytes), stage size 40960, two stages
#define A_H   0
#define A_L   10240
#define B_0H  20480
#define B_0L  25600
#define B_1H  30720
#define B_1L  35840
#define STG   40960
#define DSM   (2*STG)

// ------------------------------------------------------------------
__global__ void reset_kernel() {
    int t = threadIdx.x;
    if (t < NE) g_cnt[t] = 0;
    if (t < 160) g_done[t] = 0;
}

// NCHW -> [T,C]: fp32 (router) + bf16 hi/lo planes
__global__ __launch_bounds__(256) void transpose_pack_kernel(const float* __restrict__ hs) {
    __shared__ float tile[32][33];
    const int b = blockIdx.z, c0 = blockIdx.y * 32, s0 = blockIdx.x * 32;
    const int tx = threadIdx.x, ty = threadIdx.y;
#pragma unroll
    for (int r = 0; r < 4; r++) {
        int cc = ty + r * 8;
        tile[cc][tx] = hs[((size_t)(b * CD + c0 + cc)) * HWD + s0 + tx];
    }
    __syncthreads();
#pragma unroll
    for (int r = 0; r < 4; r++) {
        int ss = ty + r * 8;
        float v = tile[tx][ss];
        size_t idx = ((size_t)(b * HWD + s0 + ss)) * CD + c0 + tx;
        g_X[idx] = v;
        __nv_bfloat16 h, l; split_bf16(v, h, l);
        g_Xh[idx] = h; g_Xl[idx] = l;
    }
}

// all three weights in one launch; blockIdx.y selects the array
__global__ __launch_bounds__(256) void prep_all(const float* __restrict__ w1,
                                                const float* __restrict__ w3,
                                                const float* __restrict__ w2) {
    const int which = blockIdx.y;
    const float* s = (which == 0) ? w1 : (which == 1) ? w3 : w2;
    __nv_bfloat16* dh = (which == 0) ? g_W1h : (which == 1) ? g_W3h : g_W2h;
    __nv_bfloat16* dl = (which == 0) ? g_W1l : (which == 1) ? g_W3l : g_W2l;
    size_t i = ((size_t)blockIdx.x * 256 + threadIdx.x) * 4;
    float4 v = *(const float4*)(s + i);
    __nv_bfloat16 h, l;
    split_bf16(v.x, h, l); dh[i+0]=h; dl[i+0]=l;
    split_bf16(v.y, h, l); dh[i+1]=h; dl[i+1]=l;
    split_bf16(v.z, h, l); dh[i+2]=h; dl[i+2]=l;
    split_bf16(v.w, h, l); dh[i+3]=h; dl[i+3]=l;
}

// router: warp per token
__global__ __launch_bounds__(256) void router_kernel(const float* __restrict__ gw) {
    __shared__ float sg[NE * CD];
    const int tid = threadIdx.x;
    for (int i = tid; i < NE * CD; i += 256) sg[i] = gw[i];
    __syncthreads();
    const int warp = tid >> 5, lane = tid & 31;
    const int t = blockIdx.x * 8 + warp;

    float acc[NE];
#pragma unroll
    for (int e = 0; e < NE; e++) acc[e] = 0.f;
    const float* xr = g_X + (size_t)t * CD;
    for (int c = lane; c < CD; c += 32) {
        float xv = xr[c];
#pragma unroll
        for (int e = 0; e < NE; e++) acc[e] = fmaf(xv, sg[e * CD + c], acc[e]);
    }
#pragma unroll
    for (int e = 0; e < NE; e++)
#pragma unroll
        for (int off = 16; off > 0; off >>= 1)
            acc[e] += __shfl_xor_sync(0xffffffffu, acc[e], off);

    if (lane == 0) {
        float mx = acc[0];
#pragma unroll
        for (int e = 1; e < NE; e++) mx = fmaxf(mx, acc[e]);
        float p[NE];
#pragma unroll
        for (int e = 0; e < NE; e++) p[e] = expf(acc[e] - mx);
        int i0 = 0; float b0 = p[0];
#pragma unroll
        for (int e = 1; e < NE; e++) if (p[e] > b0) { b0 = p[e]; i0 = e; }
        int i1 = (i0 == 0) ? 1 : 0; float b1 = p[i1];
#pragma unroll
        for (int e = 0; e < NE; e++)
            if (e != i0 && p[e] > b1) { b1 = p[e]; i1 = e; }
        float inv = 1.f / (b0 + b1);
        g_wt[t * 2 + 0] = b0 * inv;
        g_wt[t * 2 + 1] = b1 * inv;
        int p0 = atomicAdd(&g_cnt[i0], 1);
        g_list[i0 * TT + p0] = t * 2 + 0;
        int p1 = atomicAdd(&g_cnt[i1], 1);
        g_list[i1 * TT + p1] = t * 2 + 1;
    }
}

__global__ void schedule_kernel() {
    if (threadIdx.x == 0) {
        int nt = 0;
        for (int e = 0; e < NE; e++) {
            int c = g_cnt[e];
            for (int m0 = 0; m0 < c; m0 += 128) { g_tile_e[nt] = e; g_tile_m0[nt] = m0; nt++; }
        }
        g_ntiles = nt;
    }
}

// ---- tile loaders (cp.async) ----
__device__ __forceinline__ void load_A(uint32_t sbase, const __nv_bfloat16* __restrict__ srcH,
                                       const __nv_bfloat16* __restrict__ srcL, int kstride,
                                       const int* asrc, int k0, int tid) {
#pragma unroll
    for (int i = 0; i < 4; i++) {
        int seg = tid + i * 256;
        int plane = seg >> 9;
        int rem = seg & 511;
        int row = rem >> 2, q = rem & 3;
        const __nv_bfloat16* src = (plane ? srcL : srcH) + (size_t)asrc[row] * kstride + k0 + q * 8;
        cp16(sbase + (plane ? A_L : A_H) + row * 80 + q * 16, src);
    }
}
__device__ __forceinline__ void load_B1(uint32_t sbase, int e, int n0, int k0, int tid) {
#pragma unroll
    for (int i = 0; i < 4; i++) {
        int seg = tid + i * 256;
        int mat = seg >> 9;
        int plane = (seg >> 8) & 1;
        int rem = seg & 255;
        int row = rem >> 2, q = rem & 3;
        const __nv_bfloat16* base = mat ? (plane ? g_W3l : g_W3h) : (plane ? g_W1l : g_W1h);
        const __nv_bfloat16* src = base + ((size_t)e * FD + n0 + row) * CD + k0 + q * 8;
        cp16(sbase + B_0H + mat * 10240 + plane * 5120 + row * 80 + q * 16, src);
    }
}
__device__ __forceinline__ void load_B2(uint32_t sbase, int e, int n0, int k0, int tid) {
#pragma unroll
    for (int i = 0; i < 4; i++) {
        int seg = tid + i * 256;
        int plane = seg >> 9;
        int rem = seg & 511;
        int row = rem >> 2, q = rem & 3;
        const __nv_bfloat16* base = plane ? g_W2l : g_W2h;
        const __nv_bfloat16* src = base + ((size_t)e * CD + n0 + row) * FD + k0 + q * 8;
        cp16(sbase + B_0H + plane * 10240 + row * 80 + q * 16, src);
    }
}

// ---- warp compute for one 32-k chunk: m32 x n64, 3-split ----
__device__ __forceinline__ void chunk_mma(uint32_t sbase, int bOffH, int bOffL,
                                          int mb, int lane, float acc[2][8][4]) {
    const int arow = lane & 15, akoff = ((lane >> 4) & 1) * 8;
    const int brow = ((lane >> 4) & 1) * 8 + (lane & 7);
    const int bkoff = ((lane >> 3) & 1) * 8;
#pragma unroll
    for (int kb = 0; kb < 32; kb += 16) {
        uint32_t ah[2][4], al[2][4];
#pragma unroll
        for (int mi = 0; mi < 2; mi++) {
            uint32_t off = (uint32_t)((mb + mi * 16 + arow) * 80 + (kb + akoff) * 2);
            ldsm4(ah[mi], sbase + A_H + off);
            ldsm4(al[mi], sbase + A_L + off);
        }
        uint32_t bh[8][2], bl[8][2];
#pragma unroll
        for (int n4 = 0; n4 < 4; n4++) {
            uint32_t off = (uint32_t)((n4 * 16 + brow) * 80 + (kb + bkoff) * 2);
            uint32_t t[4];
            ldsm4(t, sbase + bOffH + off);
            bh[2*n4][0]=t[0]; bh[2*n4][1]=t[1]; bh[2*n4+1][0]=t[2]; bh[2*n4+1][1]=t[3];
            ldsm4(t, sbase + bOffL + off);
            bl[2*n4][0]=t[0]; bl[2*n4][1]=t[1]; bl[2*n4+1][0]=t[2]; bl[2*n4+1][1]=t[3];
        }
#pragma unroll
        for (int mi = 0; mi < 2; mi++)
#pragma unroll
            for (int ni = 0; ni < 8; ni++) {
                mma_bf16(acc[mi][ni], ah[mi], bh[ni]);
                mma_bf16(acc[mi][ni], ah[mi], bl[ni]);
                mma_bf16(acc[mi][ni], al[mi], bh[ni]);
            }
    }
}

// ------------------------------------------------------------------
// Fused GEMM kernel: bids [0, G1_CTAS) do gemm1 tiles; the rest do gemm2
// tiles, gated on per-mtile done counters (gemm1 n-tiles each increment).
__global__ __launch_bounds__(256, 2) void moe_gemms() {
    extern __shared__ char dsm[];
    __shared__ int rows[128];
    __shared__ int asrc[128];
    __shared__ float wts[128];

    const int tid = threadIdx.x, warp = tid >> 5, lane = tid & 31;
    const int bid = blockIdx.x;
    const bool is_g1 = bid < G1_CTAS;
    const int nt = is_g1 ? (bid & (G1_NT - 1)) : ((bid - G1_CTAS) & (G2_NT - 1));
    const int mt = is_g1 ? (bid >> 4) : ((bid - G1_CTAS) >> 3);

    if (mt >= g_ntiles) {
        if (is_g1 && tid == 0) atomicAdd(&g_done[mt], 1);
        return;
    }
    const int e  = g_tile_e[mt];
    const int m0 = g_tile_m0[mt];
    const int ne = g_cnt[e];
    const uint32_t sb = smem_u32(dsm);

    if (is_g1) {
        const int n0 = nt * 64;
        if (tid < 128) {
            int i = m0 + tid;
            int ic = (i < ne) ? i : ne - 1;
            int entry = g_list[e * TT + ic];
            rows[tid] = (i < ne) ? entry : -1;
            asrc[tid] = entry >> 1;
        }
        __syncthreads();

        const int mb = (warp & 3) * 32;
        const bool isW3 = warp >= 4;
        const int bOffH = isW3 ? B_1H : B_0H;
        const int bOffL = isW3 ? B_1L : B_0L;

        float acc[2][8][4];
#pragma unroll
        for (int i = 0; i < 2; i++)
#pragma unroll
            for (int j = 0; j < 8; j++)
#pragma unroll
                for (int q = 0; q < 4; q++) acc[i][j][q] = 0.f;

        load_A(sb, g_Xh, g_Xl, CD, asrc, 0, tid);
        load_B1(sb, e, n0, 0, tid);
        CP_COMMIT();
        for (int ch = 0; ch < 32; ch++) {
            CP_WAIT0();
            __syncthreads();
            if (ch + 1 < 32) {
                uint32_t nb = sb + ((ch + 1) & 1) * STG;
                load_A(nb, g_Xh, g_Xl, CD, asrc, (ch + 1) * 32, tid);
                load_B1(nb, e, n0, (ch + 1) * 32, tid);
                CP_COMMIT();
            }
            chunk_mma(sb + (ch & 1) * STG, bOffH, bOffL, mb, lane, acc);
        }
        __syncthreads();

        float* P1 = (float*)dsm;
        float* P3 = (float*)(dsm + 33792);
        float* myP = isW3 ? P3 : P1;
#pragma unroll
        for (int mi = 0; mi < 2; mi++)
#pragma unroll
            for (int ni = 0; ni < 8; ni++) {
                int m = mb + mi * 16 + (lane >> 2);
                int n = ni * 8 + (lane & 3) * 2;
                myP[m * 66 + n]       = acc[mi][ni][0];
                myP[m * 66 + n + 1]   = acc[mi][ni][1];
                myP[(m+8) * 66 + n]   = acc[mi][ni][2];
                myP[(m+8) * 66 + n+1] = acc[mi][ni][3];
            }
        __syncthreads();
        for (int idx = tid; idx < 128 * 64; idx += 256) {
            int m = idx >> 6, n = idx & 63;
            int entry = rows[m];
            if (entry < 0) continue;
            float d1 = P1[m * 66 + n];
            float d3 = P3[m * 66 + n];
            float gl = 0.5f * d1 * (1.f + erff(d1 * 0.70710678118654752f)) * d3;
            __nv_bfloat16 h, l; split_bf16(gl, h, l);
            size_t o = (size_t)entry * FD + n0 + n;
            g_Hh[o] = h; g_Hl[o] = l;
        }
        __threadfence();
        __syncthreads();
        if (tid == 0) atomicAdd(&g_done[mt], 1);
    } else {
        const int n0 = nt * 128;
        if (tid < 128) {
            int i = m0 + tid;
            int ic = (i < ne) ? i : ne - 1;
            int entry = g_list[e * TT + ic];
            rows[tid] = (i < ne) ? entry : -1;
            asrc[tid] = entry;
            wts[tid] = (i < ne) ? g_wt[entry] : 0.f;
        }
        // prefetch W2 chunk 0 (independent of H) while waiting
        load_B2(sb, e, n0, 0, tid);
        if (tid == 0) {
            while (atomicAdd(&g_done[mt], 0) < G1_NT) __nanosleep(256);
            __threadfence();
        }
        __syncthreads();

        const int mb = (warp >> 1) * 32;
        const int nb = (warp & 1) * 64;
        const int bOffH = B_0H + (nb ? 5120 : 0);
        const int bOffL = B_0H + 10240 + (nb ? 5120 : 0);

        float acc[2][8][4];
#pragma unroll
        for (int i = 0; i < 2; i++)
#pragma unroll
            for (int j = 0; j < 8; j++)
#pragma unroll
                for (int q = 0; q < 4; q++) acc[i][j][q] = 0.f;

        load_A(sb, g_Hh, g_Hl, FD, asrc, 0, tid);
        CP_COMMIT();
        for (int ch = 0; ch < 32; ch++) {
            CP_WAIT0();
            __syncthreads();
            if (ch + 1 < 32) {
                uint32_t nbuf = sb + ((ch + 1) & 1) * STG;
                load_A(nbuf, g_Hh, g_Hl, FD, asrc, (ch + 1) * 32, tid);
                load_B2(nbuf, e, n0, (ch + 1) * 32, tid);
                CP_COMMIT();
            }
            chunk_mma(sb + (ch & 1) * STG, bOffH, bOffL, mb, lane, acc);
        }

#pragma unroll
        for (int mi = 0; mi < 2; mi++) {
            int mB = mb + mi * 16 + (lane >> 2);
#pragma unroll
            for (int half = 0; half < 2; half++) {
                int m = mB + half * 8;
                int entry = rows[m];
                if (entry < 0) continue;
                float w = wts[m];
                float* yr = g_Y + (size_t)entry * CD + n0 + nb;
#pragma unroll
                for (int ni = 0; ni < 8; ni++) {
                    int n = ni * 8 + (lane & 3) * 2;
                    float2 v = make_float2(w * acc[mi][ni][half * 2], w * acc[mi][ni][half * 2 + 1]);
                    *(float2*)(yr + n) = v;
                }
            }
        }
    }
}

// sum two slots, transpose back to NCHW
__global__ __launch_bounds__(256) void combine_out_kernel(float* __restrict__ out) {
    __shared__ float tile[32][33];
    const int b = blockIdx.z, c0 = blockIdx.y * 32, s0 = blockIdx.x * 32;
    const int tx = threadIdx.x, ty = threadIdx.y;
#pragma unroll
    for (int r = 0; r < 4; r++) {
        int ss = ty + r * 8;
        size_t t2 = (size_t)(b * HWD + s0 + ss) * 2;
        tile[ss][tx] = g_Y[t2 * CD + c0 + tx] + g_Y[(t2 + 1) * CD + c0 + tx];
    }
    __syncthreads();
#pragma unroll
    for (int r = 0; r < 4; r++) {
        int cc = ty + r * 8;
        out[((size_t)(b * CD + c0 + cc)) * HWD + s0 + tx] = tile[tx][cc];
    }
}

// ------------------------------------------------------------------
extern "C" void kernel_launch(void* const* d_in, const int* in_sizes, int n_in,
                              void* d_out, int out_size) {
    const float* hs   = (const float*)d_in[0];
    const float* gate = (const float*)d_in[1];
    const float* w1   = (const float*)d_in[2];
    const float* w2   = (const float*)d_in[3];
    const float* w3   = (const float*)d_in[4];
    float* out = (float*)d_out;

    cudaFuncSetAttribute(moe_gemms, cudaFuncAttributeMaxDynamicSharedMemorySize, DSM);

    reset_kernel<<<1, 256>>>();
    transpose_pack_kernel<<<dim3(HWD / 32, CD / 32, BD), dim3(32, 8)>>>(hs);
    prep_all<<<dim3(NE * FD * CD / 4 / 256, 3), 256>>>(w1, w3, w2);
    router_kernel<<<TT / 8, 256>>>(gate);
    schedule_kernel<<<1, 32>>>();
    moe_gemms<<<G1_CTAS + G2_CTAS, 256, DSM>>>();
    combine_out_kernel<<<dim3(HWD / 32, CD / 32, BD), dim3(32, 8)>>>(out);
}

// round 8
// speedup vs baseline: 1.3400x; 1.3400x over previous
#include <cuda_runtime.h>
#include <cuda_fp16.h>
#include <math.h>
#include <stdint.h>

#define TT   8192
#define CD   1024
#define FD   1024
#define NE   8
#define HWD  4096
#define BD   2
#define NENT (TT*2)

// ---------------- scratch (16B-aligned for cp.async / vector ld-st) ----------------
__device__ __align__(16) float  g_X  [TT * CD];
__device__ __align__(16) __half g_Xf [TT * CD];
__device__ __align__(16) __half g_W1h[NE * FD * CD];
__device__ __align__(16) __half g_W1l[NE * FD * CD];
__device__ __align__(16) __half g_W3h[NE * FD * CD];
__device__ __align__(16) __half g_W3l[NE * FD * CD];
__device__ __align__(16) __half g_W2h[NE * CD * FD];
__device__ __align__(16) __half g_W2l[NE * CD * FD];
__device__ __align__(16) __half g_Hf [NENT * FD];
__device__ __align__(16) float  g_Y  [NENT * CD];
__device__ __align__(16) float  g_wt [NENT];
__device__ int  g_cnt[NE];
__device__ __align__(16) int  g_list[NE * TT];
__device__ __align__(16) int  g_tile_e[160];
__device__ __align__(16) int  g_tile_m0[160];
__device__ int  g_ntiles;

// ---------------- helpers ----------------
__device__ __forceinline__ uint32_t smem_u32(const void* p) {
    uint32_t a;
    asm("{ .reg .u64 t; cvta.to.shared.u64 t, %1; cvt.u32.u64 %0, t; }" : "=r"(a) : "l"(p));
    return a;
}
__device__ __forceinline__ void cp16(uint32_t dst, const void* src) {
    asm volatile("cp.async.cg.shared.global [%0], [%1], 16;" :: "r"(dst), "l"(src) : "memory");
}
#define CP_COMMIT() asm volatile("cp.async.commit_group;" ::: "memory")
#define CP_WAIT1()  asm volatile("cp.async.wait_group 1;" ::: "memory")
#define CP_WAIT0()  asm volatile("cp.async.wait_group 0;" ::: "memory")

__device__ __forceinline__ void ldsm4(uint32_t* r, uint32_t a) {
    asm volatile("ldmatrix.sync.aligned.m8n8.x4.shared.b16 {%0,%1,%2,%3}, [%4];"
        : "=r"(r[0]), "=r"(r[1]), "=r"(r[2]), "=r"(r[3]) : "r"(a));
}
__device__ __forceinline__ void mma_f16(float* c, const uint32_t* a, const uint32_t* b) {
    asm volatile(
        "mma.sync.aligned.m16n8k16.row.col.f32.f16.f16.f32 "
        "{%0,%1,%2,%3}, {%4,%5,%6,%7}, {%8,%9}, {%0,%1,%2,%3};"
        : "+f"(c[0]), "+f"(c[1]), "+f"(c[2]), "+f"(c[3])
        : "r"(a[0]), "r"(a[1]), "r"(a[2]), "r"(a[3]), "r"(b[0]), "r"(b[1]));
}
__device__ __forceinline__ void split_f16(float f, __half& h, __half& l) {
    h = __float2half_rn(f);
    l = __float2half_rn(f - __half2float(h));
}

// smem stage layout (bytes), stage 30720, THREE stages
// A (1 plane): 128 rows * 80B = 10240
// B: 4 blocks of 64 rows * 80B = 5120 each (gemm1: W1h,W1l,W3h,W3l ; gemm2: W2h(128r)=2 blocks, W2l=2 blocks)
#define A_OFF 0
#define B_OFF 10240
#define STG   30720
#define DSM   (3*STG)

// ------------------------------------------------------------------
__global__ void reset_kernel() { if (threadIdx.x < NE) g_cnt[threadIdx.x] = 0; }

// NCHW -> [T,C]: fp32 (router) + fp16 plane
__global__ __launch_bounds__(256) void transpose_pack_kernel(const float* __restrict__ hs) {
    __shared__ float tile[32][33];
    const int b = blockIdx.z, c0 = blockIdx.y * 32, s0 = blockIdx.x * 32;
    const int tx = threadIdx.x, ty = threadIdx.y;
#pragma unroll
    for (int r = 0; r < 4; r++) {
        int cc = ty + r * 8;
        tile[cc][tx] = hs[((size_t)(b * CD + c0 + cc)) * HWD + s0 + tx];
    }
    __syncthreads();
#pragma unroll
    for (int r = 0; r < 4; r++) {
        int ss = ty + r * 8;
        float v = tile[tx][ss];
        size_t idx = ((size_t)(b * HWD + s0 + ss)) * CD + c0 + tx;
        g_X[idx]  = v;
        g_Xf[idx] = __float2half_rn(v);
    }
}

// all three weights in one launch; blockIdx.y selects the array
__global__ __launch_bounds__(256) void prep_all(const float* __restrict__ w1,
                                                const float* __restrict__ w3,
                                                const float* __restrict__ w2) {
    const int which = blockIdx.y;
    const float* s = (which == 0) ? w1 : (which == 1) ? w3 : w2;
    __half* dh = (which == 0) ? g_W1h : (which == 1) ? g_W3h : g_W2h;
    __half* dl = (which == 0) ? g_W1l : (which == 1) ? g_W3l : g_W2l;
    size_t i = ((size_t)blockIdx.x * 256 + threadIdx.x) * 4;
    float4 v = *(const float4*)(s + i);
    __half h0, l0, h1, l1, h2, l2, h3, l3;
    split_f16(v.x, h0, l0); split_f16(v.y, h1, l1);
    split_f16(v.z, h2, l2); split_f16(v.w, h3, l3);
    __half hbuf[4] = {h0, h1, h2, h3};
    __half lbuf[4] = {l0, l1, l2, l3};
    *(uint2*)(dh + i) = *(uint2*)hbuf;
    *(uint2*)(dl + i) = *(uint2*)lbuf;
}

// router: warp per token
__global__ __launch_bounds__(256) void router_kernel(const float* __restrict__ gw) {
    __shared__ float sg[NE * CD];
    const int tid = threadIdx.x;
    for (int i = tid; i < NE * CD; i += 256) sg[i] = gw[i];
    __syncthreads();
    const int warp = tid >> 5, lane = tid & 31;
    const int t = blockIdx.x * 8 + warp;

    float acc[NE];
#pragma unroll
    for (int e = 0; e < NE; e++) acc[e] = 0.f;
    const float* xr = g_X + (size_t)t * CD;
    for (int c = lane; c < CD; c += 32) {
        float xv = xr[c];
#pragma unroll
        for (int e = 0; e < NE; e++) acc[e] = fmaf(xv, sg[e * CD + c], acc[e]);
    }
#pragma unroll
    for (int e = 0; e < NE; e++)
#pragma unroll
        for (int off = 16; off > 0; off >>= 1)
            acc[e] += __shfl_xor_sync(0xffffffffu, acc[e], off);

    if (lane == 0) {
        float mx = acc[0];
#pragma unroll
        for (int e = 1; e < NE; e++) mx = fmaxf(mx, acc[e]);
        float p[NE];
#pragma unroll
        for (int e = 0; e < NE; e++) p[e] = expf(acc[e] - mx);
        int i0 = 0; float b0 = p[0];
#pragma unroll
        for (int e = 1; e < NE; e++) if (p[e] > b0) { b0 = p[e]; i0 = e; }
        int i1 = (i0 == 0) ? 1 : 0; float b1 = p[i1];
#pragma unroll
        for (int e = 0; e < NE; e++)
            if (e != i0 && p[e] > b1) { b1 = p[e]; i1 = e; }
        float inv = 1.f / (b0 + b1);
        g_wt[t * 2 + 0] = b0 * inv;
        g_wt[t * 2 + 1] = b1 * inv;
        int p0 = atomicAdd(&g_cnt[i0], 1);
        g_list[i0 * TT + p0] = t * 2 + 0;
        int p1 = atomicAdd(&g_cnt[i1], 1);
        g_list[i1 * TT + p1] = t * 2 + 1;
    }
}

__global__ void schedule_kernel() {
    if (threadIdx.x == 0) {
        int nt = 0;
        for (int e = 0; e < NE; e++) {
            int c = g_cnt[e];
            for (int m0 = 0; m0 < c; m0 += 128) { g_tile_e[nt] = e; g_tile_m0[nt] = m0; nt++; }
        }
        g_ntiles = nt;
    }
}

// ---- tile loaders (cp.async); fp16 single-plane A, 2-plane B ----
// A: 128 rows x 32 k -> 512 segs (2 iters)
__device__ __forceinline__ void load_A(uint32_t sbase, const __half* __restrict__ src0,
                                       int kstride, const int* asrc, int k0, int tid) {
#pragma unroll
    for (int i = 0; i < 2; i++) {
        int seg = tid + i * 256;          // 0..511
        int row = seg >> 2, q = seg & 3;  // row 0..127
        const __half* src = src0 + (size_t)asrc[row] * kstride + k0 + q * 8;
        cp16(sbase + A_OFF + row * 80 + q * 16, src);
    }
}
// B gemm1: W1h,W1l,W3h,W3l each 64 rows -> 1024 segs (4 iters)
__device__ __forceinline__ void load_B1(uint32_t sbase, int e, int n0, int k0, int tid) {
#pragma unroll
    for (int i = 0; i < 4; i++) {
        int seg = tid + i * 256;          // 0..1023
        int mat = seg >> 9;               // 0:W1 1:W3
        int plane = (seg >> 8) & 1;       // 0:h 1:l
        int rem = seg & 255;
        int row = rem >> 2, q = rem & 3;  // row 0..63
        const __half* base = mat ? (plane ? g_W3l : g_W3h) : (plane ? g_W1l : g_W1h);
        const __half* src = base + ((size_t)e * FD + n0 + row) * CD + k0 + q * 8;
        cp16(sbase + B_OFF + mat * 10240 + plane * 5120 + row * 80 + q * 16, src);
    }
}
// B gemm2: W2h,W2l each 128 rows -> 1024 segs (4 iters)
__device__ __forceinline__ void load_B2(uint32_t sbase, int e, int n0, int k0, int tid) {
#pragma unroll
    for (int i = 0; i < 4; i++) {
        int seg = tid + i * 256;
        int plane = seg >> 9;             // 0:h 1:l
        int rem = seg & 511;
        int row = rem >> 2, q = rem & 3;  // row 0..127
        const __half* base = plane ? g_W2l : g_W2h;
        const __half* src = base + ((size_t)e * CD + n0 + row) * FD + k0 + q * 8;
        cp16(sbase + B_OFF + plane * 10240 + row * 80 + q * 16, src);
    }
}

// ---- warp compute for one 32-k chunk: m32 x n64, A 1-plane x B 2-plane ----
__device__ __forceinline__ void chunk_mma(uint32_t sbase, int bOffH, int bOffL,
                                          int mb, int lane, float acc[2][8][4]) {
    const int arow = lane & 15, akoff = ((lane >> 4) & 1) * 8;
    const int brow = ((lane >> 4) & 1) * 8 + (lane & 7);
    const int bkoff = ((lane >> 3) & 1) * 8;
#pragma unroll
    for (int kb = 0; kb < 32; kb += 16) {
        uint32_t a[2][4];
#pragma unroll
        for (int mi = 0; mi < 2; mi++) {
            uint32_t off = (uint32_t)((mb + mi * 16 + arow) * 80 + (kb + akoff) * 2);
            ldsm4(a[mi], sbase + A_OFF + off);
        }
        uint32_t bh[8][2], bl[8][2];
#pragma unroll
        for (int n4 = 0; n4 < 4; n4++) {
            uint32_t off = (uint32_t)((n4 * 16 + brow) * 80 + (kb + bkoff) * 2);
            uint32_t t[4];
            ldsm4(t, sbase + bOffH + off);
            bh[2*n4][0]=t[0]; bh[2*n4][1]=t[1]; bh[2*n4+1][0]=t[2]; bh[2*n4+1][1]=t[3];
            ldsm4(t, sbase + bOffL + off);
            bl[2*n4][0]=t[0]; bl[2*n4][1]=t[1]; bl[2*n4+1][0]=t[2]; bl[2*n4+1][1]=t[3];
        }
#pragma unroll
        for (int mi = 0; mi < 2; mi++)
#pragma unroll
            for (int ni = 0; ni < 8; ni++) {
                mma_f16(acc[mi][ni], a[mi], bh[ni]);
                mma_f16(acc[mi][ni], a[mi], bl[ni]);
            }
    }
}

// 3-stage pipeline driver macro-ish: wait for chunk ch with 1 group in flight
#define PIPE_WAIT(ch) do { if ((ch) == 31) { CP_WAIT0(); } else { CP_WAIT1(); } } while (0)

// ------------------------------------------------------------------
// GEMM1: 128 rows x 64 ffn cols; warps 0-3 -> W1, warps 4-7 -> W3
__global__ __launch_bounds__(256, 2) void gemm1_mma() {
    if (blockIdx.y >= g_ntiles) return;
    extern __shared__ char dsm[];
    __shared__ int rows[128];
    __shared__ int asrc[128];

    const int tid = threadIdx.x, warp = tid >> 5, lane = tid & 31;
    const int e  = g_tile_e[blockIdx.y];
    const int m0 = g_tile_m0[blockIdx.y];
    const int ne = g_cnt[e];
    const int n0 = blockIdx.x * 64;

    if (tid < 128) {
        int i = m0 + tid;
        int ic = (i < ne) ? i : ne - 1;
        int entry = g_list[e * TT + ic];
        rows[tid] = (i < ne) ? entry : -1;
        asrc[tid] = entry >> 1;
    }
    __syncthreads();

    const uint32_t sb = smem_u32(dsm);
    const int mb = (warp & 3) * 32;
    const bool isW3 = warp >= 4;
    const int bOffH = B_OFF + (isW3 ? 10240 : 0);
    const int bOffL = bOffH + 5120;

    float acc[2][8][4];
#pragma unroll
    for (int i = 0; i < 2; i++)
#pragma unroll
        for (int j = 0; j < 8; j++)
#pragma unroll
            for (int q = 0; q < 4; q++) acc[i][j][q] = 0.f;

    load_A(sb, g_Xf, CD, asrc, 0, tid);  load_B1(sb, e, n0, 0, tid);  CP_COMMIT();
    load_A(sb + STG, g_Xf, CD, asrc, 32, tid); load_B1(sb + STG, e, n0, 32, tid); CP_COMMIT();
    for (int ch = 0; ch < 32; ch++) {
        PIPE_WAIT(ch);
        __syncthreads();
        if (ch + 2 < 32) {
            uint32_t nb = sb + ((ch + 2) % 3) * STG;
            load_A(nb, g_Xf, CD, asrc, (ch + 2) * 32, tid);
            load_B1(nb, e, n0, (ch + 2) * 32, tid);
            CP_COMMIT();
        }
        chunk_mma(sb + (ch % 3) * STG, bOffH, bOffL, mb, lane, acc);
    }
    __syncthreads();

    // epilogue: exchange P1/P3 via smem, gelu*mul, store H fp16
    float* P1 = (float*)dsm;
    float* P3 = (float*)(dsm + 33792);
    float* myP = isW3 ? P3 : P1;
#pragma unroll
    for (int mi = 0; mi < 2; mi++)
#pragma unroll
        for (int ni = 0; ni < 8; ni++) {
            int m = mb + mi * 16 + (lane >> 2);
            int n = ni * 8 + (lane & 3) * 2;
            myP[m * 66 + n]       = acc[mi][ni][0];
            myP[m * 66 + n + 1]   = acc[mi][ni][1];
            myP[(m+8) * 66 + n]   = acc[mi][ni][2];
            myP[(m+8) * 66 + n+1] = acc[mi][ni][3];
        }
    __syncthreads();
    for (int idx = tid; idx < 128 * 64; idx += 256) {
        int m = idx >> 6, n = idx & 63;
        int entry = rows[m];
        if (entry < 0) continue;
        float d1 = P1[m * 66 + n];
        float d3 = P3[m * 66 + n];
        float gl = 0.5f * d1 * (1.f + erff(d1 * 0.70710678118654752f)) * d3;
        g_Hf[(size_t)entry * FD + n0 + n] = __float2half_rn(gl);
    }
}

// GEMM2: 128 rows x 128 out cols; warp grid 4(m) x 2(n)
__global__ __launch_bounds__(256, 2) void gemm2_mma() {
    if (blockIdx.y >= g_ntiles) return;
    extern __shared__ char dsm[];
    __shared__ int rows[128];
    __shared__ int asrc[128];
    __shared__ float wts[128];

    const int tid = threadIdx.x, warp = tid >> 5, lane = tid & 31;
    const int e  = g_tile_e[blockIdx.y];
    const int m0 = g_tile_m0[blockIdx.y];
    const int ne = g_cnt[e];
    const int n0 = blockIdx.x * 128;

    if (tid < 128) {
        int i = m0 + tid;
        int ic = (i < ne) ? i : ne - 1;
        int entry = g_list[e * TT + ic];
        rows[tid] = (i < ne) ? entry : -1;
        asrc[tid] = entry;
        wts[tid] = (i < ne) ? g_wt[entry] : 0.f;
    }
    __syncthreads();

    const uint32_t sb = smem_u32(dsm);
    const int mb = (warp >> 1) * 32;
    const int nb = (warp & 1) * 64;
    const int bOffH = B_OFF + (nb ? 5120 : 0);
    const int bOffL = B_OFF + 10240 + (nb ? 5120 : 0);

    float acc[2][8][4];
#pragma unroll
    for (int i = 0; i < 2; i++)
#pragma unroll
        for (int j = 0; j < 8; j++)
#pragma unroll
            for (int q = 0; q < 4; q++) acc[i][j][q] = 0.f;

    load_A(sb, g_Hf, FD, asrc, 0, tid);  load_B2(sb, e, n0, 0, tid);  CP_COMMIT();
    load_A(sb + STG, g_Hf, FD, asrc, 32, tid); load_B2(sb + STG, e, n0, 32, tid); CP_COMMIT();
    for (int ch = 0; ch < 32; ch++) {
        PIPE_WAIT(ch);
        __syncthreads();
        if (ch + 2 < 32) {
            uint32_t nbuf = sb + ((ch + 2) % 3) * STG;
            load_A(nbuf, g_Hf, FD, asrc, (ch + 2) * 32, tid);
            load_B2(nbuf, e, n0, (ch + 2) * 32, tid);
            CP_COMMIT();
        }
        chunk_mma(sb + (ch % 3) * STG, bOffH, bOffL, mb, lane, acc);
    }

    // epilogue: scale by routing weight, store Y directly
#pragma unroll
    for (int mi = 0; mi < 2; mi++) {
        int mB = mb + mi * 16 + (lane >> 2);
#pragma unroll
        for (int half = 0; half < 2; half++) {
            int m = mB + half * 8;
            int entry = rows[m];
            if (entry < 0) continue;
            float w = wts[m];
            float* yr = g_Y + (size_t)entry * CD + n0 + nb;
#pragma unroll
            for (int ni = 0; ni < 8; ni++) {
                int n = ni * 8 + (lane & 3) * 2;
                float2 v = make_float2(w * acc[mi][ni][half * 2], w * acc[mi][ni][half * 2 + 1]);
                *(float2*)(yr + n) = v;
            }
        }
    }
}

// sum two slots, transpose back to NCHW
__global__ __launch_bounds__(256) void combine_out_kernel(float* __restrict__ out) {
    __shared__ float tile[32][33];
    const int b = blockIdx.z, c0 = blockIdx.y * 32, s0 = blockIdx.x * 32;
    const int tx = threadIdx.x, ty = threadIdx.y;
#pragma unroll
    for (int r = 0; r < 4; r++) {
        int ss = ty + r * 8;
        size_t t2 = (size_t)(b * HWD + s0 + ss) * 2;
        tile[ss][tx] = g_Y[t2 * CD + c0 + tx] + g_Y[(t2 + 1) * CD + c0 + tx];
    }
    __syncthreads();
#pragma unroll
    for (int r = 0; r < 4; r++) {
        int cc = ty + r * 8;
        out[((size_t)(b * CD + c0 + cc)) * HWD + s0 + tx] = tile[tx][cc];
    }
}

// ------------------------------------------------------------------
extern "C" void kernel_launch(void* const* d_in, const int* in_sizes, int n_in,
                              void* d_out, int out_size) {
    const float* hs   = (const float*)d_in[0];
    const float* gate = (const float*)d_in[1];
    const float* w1   = (const float*)d_in[2];
    const float* w2   = (const float*)d_in[3];
    const float* w3   = (const float*)d_in[4];
    float* out = (float*)d_out;

    cudaFuncSetAttribute(gemm1_mma, cudaFuncAttributeMaxDynamicSharedMemorySize, DSM);
    cudaFuncSetAttribute(gemm2_mma, cudaFuncAttributeMaxDynamicSharedMemorySize, DSM);

    reset_kernel<<<1, 32>>>();
    transpose_pack_kernel<<<dim3(HWD / 32, CD / 32, BD), dim3(32, 8)>>>(hs);
    prep_all<<<dim3(NE * FD * CD / 4 / 256, 3), 256>>>(w1, w3, w2);
    router_kernel<<<TT / 8, 256>>>(gate);
    schedule_kernel<<<1, 32>>>();
    gemm1_mma<<<dim3(FD / 64, 136), 256, DSM>>>();
    gemm2_mma<<<dim3(CD / 128, 136), 256, DSM>>>();
    combine_out_kernel<<<dim3(HWD / 32, CD / 32, BD), dim3(32, 8)>>>(out);
}

// round 10
// speedup vs baseline: 2.1479x; 1.6030x over previous
#include <cuda_runtime.h>
#include <cuda_fp16.h>
#include <math.h>
#include <stdint.h>

#define TT   8192
#define CD   1024
#define FD   1024
#define NE   8
#define HWD  4096
#define BD   2
#define NENT (TT*2)

// ---------------- scratch (16B-aligned for cp.async / vector ld-st) ----------------
__device__ __align__(16) float  g_X  [TT * CD];   // fp32 tokens: ROUTER ONLY (top-k needs full precision)
__device__ __align__(16) __half g_Xf [TT * CD];   // fp16 tokens: GEMM A operand
__device__ __align__(16) __half g_W1 [NE * FD * CD];
__device__ __align__(16) __half g_W3 [NE * FD * CD];
__device__ __align__(16) __half g_W2 [NE * CD * FD];
__device__ __align__(16) __half g_Hf [NENT * FD];
__device__ __align__(16) __half g_Yf [NENT * CD];
__device__ __align__(16) float  g_wt [NENT];
__device__ int  g_cnt[NE];
__device__ __align__(16) int  g_list[NE * TT];
__device__ __align__(16) int  g_tile_e[160];
__device__ __align__(16) int  g_tile_m0[160];
__device__ int  g_ntiles;

// ---------------- helpers ----------------
__device__ __forceinline__ uint32_t smem_u32(const void* p) {
    uint32_t a;
    asm("{ .reg .u64 t; cvta.to.shared.u64 t, %1; cvt.u32.u64 %0, t; }" : "=r"(a) : "l"(p));
    return a;
}
__device__ __forceinline__ void cp16(uint32_t dst, const void* src) {
    asm volatile("cp.async.cg.shared.global [%0], [%1], 16;" :: "r"(dst), "l"(src) : "memory");
}
#define CP_COMMIT() asm volatile("cp.async.commit_group;" ::: "memory")
#define CP_WAIT2()  asm volatile("cp.async.wait_group 2;" ::: "memory")
#define CP_WAIT1()  asm volatile("cp.async.wait_group 1;" ::: "memory")
#define CP_WAIT0()  asm volatile("cp.async.wait_group 0;" ::: "memory")
// 4-stage: keep up to 3 groups in flight, guarantee chunk ch is resident
#define PIPE_WAIT(ch) do { if ((ch) <= 29) { CP_WAIT2(); } else if ((ch) == 30) { CP_WAIT1(); } else { CP_WAIT0(); } } while (0)

__device__ __forceinline__ void ldsm4(uint32_t* r, uint32_t a) {
    asm volatile("ldmatrix.sync.aligned.m8n8.x4.shared.b16 {%0,%1,%2,%3}, [%4];"
        : "=r"(r[0]), "=r"(r[1]), "=r"(r[2]), "=r"(r[3]) : "r"(a));
}
__device__ __forceinline__ void mma_f16(float* c, const uint32_t* a, const uint32_t* b) {
    asm volatile(
        "mma.sync.aligned.m16n8k16.row.col.f32.f16.f16.f32 "
        "{%0,%1,%2,%3}, {%4,%5,%6,%7}, {%8,%9}, {%0,%1,%2,%3};"
        : "+f"(c[0]), "+f"(c[1]), "+f"(c[2]), "+f"(c[3])
        : "r"(a[0]), "r"(a[1]), "r"(a[2]), "r"(a[3]), "r"(b[0]), "r"(b[1]));
}

// smem stage layout (bytes), stage 20480, FOUR stages
// A: 128 rows * 80B = 10240 ; B: 128 rows total * 80B = 10240
#define A_OFF 0
#define B_OFF 10240
#define STG   20480
#define DSM   (4*STG)

// ------------------------------------------------------------------
__global__ void reset_kernel() { if (threadIdx.x < NE) g_cnt[threadIdx.x] = 0; }

// NCHW -> [T,C]: fp32 plane (router) + fp16 plane (GEMM)
__global__ __launch_bounds__(256) void transpose_pack_kernel(const float* __restrict__ hs) {
    __shared__ float tile[32][33];
    const int b = blockIdx.z, c0 = blockIdx.y * 32, s0 = blockIdx.x * 32;
    const int tx = threadIdx.x, ty = threadIdx.y;
#pragma unroll
    for (int r = 0; r < 4; r++) {
        int cc = ty + r * 8;
        tile[cc][tx] = hs[((size_t)(b * CD + c0 + cc)) * HWD + s0 + tx];
    }
    __syncthreads();
#pragma unroll
    for (int r = 0; r < 4; r++) {
        int ss = ty + r * 8;
        float v = tile[tx][ss];
        size_t idx = ((size_t)(b * HWD + s0 + ss)) * CD + c0 + tx;
        g_X[idx]  = v;
        g_Xf[idx] = __float2half_rn(v);
    }
}

// all three weights, single fp16 plane; blockIdx.y selects the array
__global__ __launch_bounds__(256) void prep_all(const float* __restrict__ w1,
                                                const float* __restrict__ w3,
                                                const float* __restrict__ w2) {
    const int which = blockIdx.y;
    const float* s = (which == 0) ? w1 : (which == 1) ? w3 : w2;
    __half* dh = (which == 0) ? g_W1 : (which == 1) ? g_W3 : g_W2;
    size_t i = ((size_t)blockIdx.x * 256 + threadIdx.x) * 4;
    float4 v = *(const float4*)(s + i);
    __half hbuf[4] = { __float2half_rn(v.x), __float2half_rn(v.y),
                       __float2half_rn(v.z), __float2half_rn(v.w) };
    *(uint2*)(dh + i) = *(uint2*)hbuf;
}

// router: warp per token, FP32 inputs (top-k selection is quantization-sensitive)
__global__ __launch_bounds__(256) void router_kernel(const float* __restrict__ gw) {
    __shared__ float sg[NE * CD];
    const int tid = threadIdx.x;
    for (int i = tid; i < NE * CD; i += 256) sg[i] = gw[i];
    __syncthreads();
    const int warp = tid >> 5, lane = tid & 31;
    const int t = blockIdx.x * 8 + warp;

    float acc[NE];
#pragma unroll
    for (int e = 0; e < NE; e++) acc[e] = 0.f;
    const float* xr = g_X + (size_t)t * CD;
    for (int c = lane; c < CD; c += 32) {
        float xv = xr[c];
#pragma unroll
        for (int e = 0; e < NE; e++) acc[e] = fmaf(xv, sg[e * CD + c], acc[e]);
    }
#pragma unroll
    for (int e = 0; e < NE; e++)
#pragma unroll
        for (int off = 16; off > 0; off >>= 1)
            acc[e] += __shfl_xor_sync(0xffffffffu, acc[e], off);

    if (lane == 0) {
        float mx = acc[0];
#pragma unroll
        for (int e = 1; e < NE; e++) mx = fmaxf(mx, acc[e]);
        float p[NE];
#pragma unroll
        for (int e = 0; e < NE; e++) p[e] = expf(acc[e] - mx);
        int i0 = 0; float b0 = p[0];
#pragma unroll
        for (int e = 1; e < NE; e++) if (p[e] > b0) { b0 = p[e]; i0 = e; }
        int i1 = (i0 == 0) ? 1 : 0; float b1 = p[i1];
#pragma unroll
        for (int e = 0; e < NE; e++)
            if (e != i0 && p[e] > b1) { b1 = p[e]; i1 = e; }
        float inv = 1.f / (b0 + b1);
        g_wt[t * 2 + 0] = b0 * inv;
        g_wt[t * 2 + 1] = b1 * inv;
        int p0 = atomicAdd(&g_cnt[i0], 1);
        g_list[i0 * TT + p0] = t * 2 + 0;
        int p1 = atomicAdd(&g_cnt[i1], 1);
        g_list[i1 * TT + p1] = t * 2 + 1;
    }
}

__global__ void schedule_kernel() {
    if (threadIdx.x == 0) {
        int nt = 0;
        for (int e = 0; e < NE; e++) {
            int c = g_cnt[e];
            for (int m0 = 0; m0 < c; m0 += 128) { g_tile_e[nt] = e; g_tile_m0[nt] = m0; nt++; }
        }
        g_ntiles = nt;
    }
}

// ---- tile loaders (cp.async), single fp16 plane ----
__device__ __forceinline__ void load_A(uint32_t sbase, const __half* __restrict__ src0,
                                       int kstride, const int* asrc, int k0, int tid) {
#pragma unroll
    for (int i = 0; i < 2; i++) {
        int seg = tid + i * 256;
        int row = seg >> 2, q = seg & 3;  // row 0..127
        const __half* src = src0 + (size_t)asrc[row] * kstride + k0 + q * 8;
        cp16(sbase + A_OFF + row * 80 + q * 16, src);
    }
}
__device__ __forceinline__ void load_B1(uint32_t sbase, int e, int n0, int k0, int tid) {
#pragma unroll
    for (int i = 0; i < 2; i++) {
        int seg = tid + i * 256;          // 0..511
        int mat = seg >> 8;               // 0:W1 1:W3
        int rem = seg & 255;
        int row = rem >> 2, q = rem & 3;  // row 0..63
        const __half* base = mat ? g_W3 : g_W1;
        const __half* src = base + ((size_t)e * FD + n0 + row) * CD + k0 + q * 8;
        cp16(sbase + B_OFF + mat * 5120 + row * 80 + q * 16, src);
    }
}
__device__ __forceinline__ void load_B2(uint32_t sbase, int e, int n0, int k0, int tid) {
#pragma unroll
    for (int i = 0; i < 2; i++) {
        int seg = tid + i * 256;
        int row = (seg & 511) >> 2, q = seg & 3;  // row 0..127
        const __half* src = g_W2 + ((size_t)e * CD + n0 + row) * FD + k0 + q * 8;
        cp16(sbase + B_OFF + row * 80 + q * 16, src);
    }
}

// ---- warp compute for one 32-k chunk: m32 x n64, single plane ----
__device__ __forceinline__ void chunk_mma(uint32_t sbase, int bOff,
                                          int mb, int lane, float acc[2][8][4]) {
    const int arow = lane & 15, akoff = ((lane >> 4) & 1) * 8;
    const int brow = ((lane >> 4) & 1) * 8 + (lane & 7);
    const int bkoff = ((lane >> 3) & 1) * 8;
#pragma unroll
    for (int kb = 0; kb < 32; kb += 16) {
        uint32_t a[2][4];
#pragma unroll
        for (int mi = 0; mi < 2; mi++) {
            uint32_t off = (uint32_t)((mb + mi * 16 + arow) * 80 + (kb + akoff) * 2);
            ldsm4(a[mi], sbase + A_OFF + off);
        }
        uint32_t bf[8][2];
#pragma unroll
        for (int n4 = 0; n4 < 4; n4++) {
            uint32_t off = (uint32_t)((n4 * 16 + brow) * 80 + (kb + bkoff) * 2);
            uint32_t t[4];
            ldsm4(t, sbase + bOff + off);
            bf[2*n4][0]=t[0]; bf[2*n4][1]=t[1]; bf[2*n4+1][0]=t[2]; bf[2*n4+1][1]=t[3];
        }
#pragma unroll
        for (int mi = 0; mi < 2; mi++)
#pragma unroll
            for (int ni = 0; ni < 8; ni++)
                mma_f16(acc[mi][ni], a[mi], bf[ni]);
    }
}

// ------------------------------------------------------------------
// GEMM1: 128 rows x 64 ffn cols; warps 0-3 -> W1, warps 4-7 -> W3
__global__ __launch_bounds__(256, 2) void gemm1_mma() {
    if (blockIdx.y >= g_ntiles) return;
    extern __shared__ char dsm[];
    __shared__ int rows[128];
    __shared__ int asrc[128];

    const int tid = threadIdx.x, warp = tid >> 5, lane = tid & 31;
    const int e  = g_tile_e[blockIdx.y];
    const int m0 = g_tile_m0[blockIdx.y];
    const int ne = g_cnt[e];
    const int n0 = blockIdx.x * 64;

    if (tid < 128) {
        int i = m0 + tid;
        int ic = (i < ne) ? i : ne - 1;
        int entry = g_list[e * TT + ic];
        rows[tid] = (i < ne) ? entry : -1;
        asrc[tid] = entry >> 1;
    }
    __syncthreads();

    const uint32_t sb = smem_u32(dsm);
    const int mb = (warp & 3) * 32;
    const bool isW3 = warp >= 4;
    const int bOff = B_OFF + (isW3 ? 5120 : 0);

    float acc[2][8][4];
#pragma unroll
    for (int i = 0; i < 2; i++)
#pragma unroll
        for (int j = 0; j < 8; j++)
#pragma unroll
            for (int q = 0; q < 4; q++) acc[i][j][q] = 0.f;

#pragma unroll
    for (int pf = 0; pf < 3; pf++) {
        load_A(sb + pf * STG, g_Xf, CD, asrc, pf * 32, tid);
        load_B1(sb + pf * STG, e, n0, pf * 32, tid);
        CP_COMMIT();
    }
    for (int ch = 0; ch < 32; ch++) {
        PIPE_WAIT(ch);
        __syncthreads();
        if (ch + 3 < 32) {
            uint32_t nb = sb + ((ch + 3) & 3) * STG;
            load_A(nb, g_Xf, CD, asrc, (ch + 3) * 32, tid);
            load_B1(nb, e, n0, (ch + 3) * 32, tid);
            CP_COMMIT();
        }
        chunk_mma(sb + (ch & 3) * STG, bOff, mb, lane, acc);
    }
    __syncthreads();

    // epilogue: exchange P1/P3 via smem, gelu*mul, store H fp16
    float* P1 = (float*)dsm;
    float* P3 = (float*)(dsm + 33792);
    float* myP = isW3 ? P3 : P1;
#pragma unroll
    for (int mi = 0; mi < 2; mi++)
#pragma unroll
        for (int ni = 0; ni < 8; ni++) {
            int m = mb + mi * 16 + (lane >> 2);
            int n = ni * 8 + (lane & 3) * 2;
            myP[m * 66 + n]       = acc[mi][ni][0];
            myP[m * 66 + n + 1]   = acc[mi][ni][1];
            myP[(m+8) * 66 + n]   = acc[mi][ni][2];
            myP[(m+8) * 66 + n+1] = acc[mi][ni][3];
        }
    __syncthreads();
    for (int idx = tid; idx < 128 * 64; idx += 256) {
        int m = idx >> 6, n = idx & 63;
        int entry = rows[m];
        if (entry < 0) continue;
        float d1 = P1[m * 66 + n];
        float d3 = P3[m * 66 + n];
        float gl = 0.5f * d1 * (1.f + erff(d1 * 0.70710678118654752f)) * d3;
        g_Hf[(size_t)entry * FD + n0 + n] = __float2half_rn(gl);
    }
}

// GEMM2: 128 rows x 128 out cols; warp grid 4(m) x 2(n)
__global__ __launch_bounds__(256, 2) void gemm2_mma() {
    if (blockIdx.y >= g_ntiles) return;
    extern __shared__ char dsm[];
    __shared__ int rows[128];
    __shared__ int asrc[128];
    __shared__ float wts[128];

    const int tid = threadIdx.x, warp = tid >> 5, lane = tid & 31;
    const int e  = g_tile_e[blockIdx.y];
    const int m0 = g_tile_m0[blockIdx.y];
    const int ne = g_cnt[e];
    const int n0 = blockIdx.x * 128;

    if (tid < 128) {
        int i = m0 + tid;
        int ic = (i < ne) ? i : ne - 1;
        int entry = g_list[e * TT + ic];
        rows[tid] = (i < ne) ? entry : -1;
        asrc[tid] = entry;
        wts[tid] = (i < ne) ? g_wt[entry] : 0.f;
    }
    __syncthreads();

    const uint32_t sb = smem_u32(dsm);
    const int mb = (warp >> 1) * 32;
    const int nb = (warp & 1) * 64;
    const int bOff = B_OFF + (nb ? 5120 : 0);

    float acc[2][8][4];
#pragma unroll
    for (int i = 0; i < 2; i++)
#pragma unroll
        for (int j = 0; j < 8; j++)
#pragma unroll
            for (int q = 0; q < 4; q++) acc[i][j][q] = 0.f;

#pragma unroll
    for (int pf = 0; pf < 3; pf++) {
        load_A(sb + pf * STG, g_Hf, FD, asrc, pf * 32, tid);
        load_B2(sb + pf * STG, e, n0, pf * 32, tid);
        CP_COMMIT();
    }
    for (int ch = 0; ch < 32; ch++) {
        PIPE_WAIT(ch);
        __syncthreads();
        if (ch + 3 < 32) {
            uint32_t nbuf = sb + ((ch + 3) & 3) * STG;
            load_A(nbuf, g_Hf, FD, asrc, (ch + 3) * 32, tid);
            load_B2(nbuf, e, n0, (ch + 3) * 32, tid);
            CP_COMMIT();
        }
        chunk_mma(sb + (ch & 3) * STG, bOff, mb, lane, acc);
    }

    // epilogue: scale by routing weight, store Y fp16
#pragma unroll
    for (int mi = 0; mi < 2; mi++) {
        int mB = mb + mi * 16 + (lane >> 2);
#pragma unroll
        for (int half = 0; half < 2; half++) {
            int m = mB + half * 8;
            int entry = rows[m];
            if (entry < 0) continue;
            float w = wts[m];
            __half* yr = g_Yf + (size_t)entry * CD + n0 + nb;
#pragma unroll
            for (int ni = 0; ni < 8; ni++) {
                int n = ni * 8 + (lane & 3) * 2;
                *(__half2*)(yr + n) = __floats2half2_rn(w * acc[mi][ni][half * 2],
                                                        w * acc[mi][ni][half * 2 + 1]);
            }
        }
    }
}

// sum two slots (fp16), transpose back to NCHW fp32
__global__ __launch_bounds__(256) void combine_out_kernel(float* __restrict__ out) {
    __shared__ float tile[32][33];
    const int b = blockIdx.z, c0 = blockIdx.y * 32, s0 = blockIdx.x * 32;
    const int tx = threadIdx.x, ty = threadIdx.y;
#pragma unroll
    for (int r = 0; r < 4; r++) {
        int ss = ty + r * 8;
        size_t t2 = (size_t)(b * HWD + s0 + ss) * 2;
        tile[ss][tx] = __half2float(g_Yf[t2 * CD + c0 + tx]) +
                       __half2float(g_Yf[(t2 + 1) * CD + c0 + tx]);
    }
    __syncthreads();
#pragma unroll
    for (int r = 0; r < 4; r++) {
        int cc = ty + r * 8;
        out[((size_t)(b * CD + c0 + cc)) * HWD + s0 + tx] = tile[tx][cc];
    }
}

// ------------------------------------------------------------------
extern "C" void kernel_launch(void* const* d_in, const int* in_sizes, int n_in,
                              void* d_out, int out_size) {
    const float* hs   = (const float*)d_in[0];
    const float* gate = (const float*)d_in[1];
    const float* w1   = (const float*)d_in[2];
    const float* w2   = (const float*)d_in[3];
    const float* w3   = (const float*)d_in[4];
    float* out = (float*)d_out;

    cudaFuncSetAttribute(gemm1_mma, cudaFuncAttributeMaxDynamicSharedMemorySize, DSM);
    cudaFuncSetAttribute(gemm2_mma, cudaFuncAttributeMaxDynamicSharedMemorySize, DSM);

    reset_kernel<<<1, 32>>>();
    transpose_pack_kernel<<<dim3(HWD / 32, CD / 32, BD), dim3(32, 8)>>>(hs);
    prep_all<<<dim3(NE * FD * CD / 4 / 256, 3), 256>>>(w1, w3, w2);
    router_kernel<<<TT / 8, 256>>>(gate);
    schedule_kernel<<<1, 32>>>();
    gemm1_mma<<<dim3(FD / 64, 136), 256, DSM>>>();
    gemm2_mma<<<dim3(CD / 128, 136), 256, DSM>>>();
    combine_out_kernel<<<dim3(HWD / 32, CD / 32, BD), dim3(32, 8)>>>(out);
}

// round 11
// speedup vs baseline: 2.3699x; 1.1033x over previous
#include <cuda_runtime.h>
#include <cuda_fp16.h>
#include <math.h>
#include <stdint.h>

#define TT   8192
#define CD   1024
#define FD   1024
#define NE   8
#define HWD  4096
#define BD   2
#define NENT (TT*2)

// ---------------- scratch (16B-aligned for cp.async / vector ld-st) ----------------
__device__ __align__(16) float  g_X  [TT * CD];   // fp32 tokens: ROUTER ONLY
__device__ __align__(16) __half g_Xf [TT * CD];   // fp16 tokens: GEMM A operand
__device__ __align__(16) __half g_W1 [NE * FD * CD];
__device__ __align__(16) __half g_W3 [NE * FD * CD];
__device__ __align__(16) __half g_W2 [NE * CD * FD];
__device__ __align__(16) __half g_Hf [NENT * FD];
__device__ __align__(16) __half g_Yf [NENT * CD];
__device__ __align__(16) float  g_wt [NENT];
__device__ int  g_cnt[NE];
__device__ __align__(16) int  g_list[NE * TT];
__device__ __align__(16) int  g_tile_e[160];
__device__ __align__(16) int  g_tile_m0[160];
__device__ int  g_ntiles;

// ---------------- helpers ----------------
__device__ __forceinline__ uint32_t smem_u32(const void* p) {
    uint32_t a;
    asm("{ .reg .u64 t; cvta.to.shared.u64 t, %1; cvt.u32.u64 %0, t; }" : "=r"(a) : "l"(p));
    return a;
}
__device__ __forceinline__ void cp16(uint32_t dst, const void* src) {
    asm volatile("cp.async.cg.shared.global [%0], [%1], 16;" :: "r"(dst), "l"(src) : "memory");
}
#define CP_COMMIT() asm volatile("cp.async.commit_group;" ::: "memory")
#define CP_WAIT1()  asm volatile("cp.async.wait_group 1;" ::: "memory")
#define CP_WAIT0()  asm volatile("cp.async.wait_group 0;" ::: "memory")
// 3-stage, 16 chunks: chunk ch resident when ≤1 newer group in flight
#define PIPE_WAIT(ch) do { if ((ch) < 15) { CP_WAIT1(); } else { CP_WAIT0(); } } while (0)

// SW128 swizzle: conflict-free ldmatrix on 128B rows, composes with 16B cp.async
__device__ __forceinline__ uint32_t sw128(uint32_t o) { return o ^ ((o >> 3) & 0x70); }

__device__ __forceinline__ void ldsm4(uint32_t* r, uint32_t a) {
    asm volatile("ldmatrix.sync.aligned.m8n8.x4.shared.b16 {%0,%1,%2,%3}, [%4];"
        : "=r"(r[0]), "=r"(r[1]), "=r"(r[2]), "=r"(r[3]) : "r"(a));
}
__device__ __forceinline__ void mma_f16(float* c, const uint32_t* a, const uint32_t* b) {
    asm volatile(
        "mma.sync.aligned.m16n8k16.row.col.f32.f16.f16.f32 "
        "{%0,%1,%2,%3}, {%4,%5,%6,%7}, {%8,%9}, {%0,%1,%2,%3};"
        : "+f"(c[0]), "+f"(c[1]), "+f"(c[2]), "+f"(c[3])
        : "r"(a[0]), "r"(a[1]), "r"(a[2]), "r"(a[3]), "r"(b[0]), "r"(b[1]));
}

// smem stage layout (bytes), K-chunk 64, stage 32768, THREE stages
// A: 128 rows * 128B = 16384 ; B: 128 rows * 128B = 16384 (gemm1: W1 64r @0 + W3 64r @8192)
#define A_OFF 0
#define B_OFF 16384
#define STG   32768
#define DSM   (3*STG)   // 98304

// ------------------------------------------------------------------
__global__ void reset_kernel() { if (threadIdx.x < NE) g_cnt[threadIdx.x] = 0; }

// NCHW -> [T,C]: fp32 plane (router) + fp16 plane (GEMM)
__global__ __launch_bounds__(256) void transpose_pack_kernel(const float* __restrict__ hs) {
    __shared__ float tile[32][33];
    const int b = blockIdx.z, c0 = blockIdx.y * 32, s0 = blockIdx.x * 32;
    const int tx = threadIdx.x, ty = threadIdx.y;
#pragma unroll
    for (int r = 0; r < 4; r++) {
        int cc = ty + r * 8;
        tile[cc][tx] = hs[((size_t)(b * CD + c0 + cc)) * HWD + s0 + tx];
    }
    __syncthreads();
#pragma unroll
    for (int r = 0; r < 4; r++) {
        int ss = ty + r * 8;
        float v = tile[tx][ss];
        size_t idx = ((size_t)(b * HWD + s0 + ss)) * CD + c0 + tx;
        g_X[idx]  = v;
        g_Xf[idx] = __float2half_rn(v);
    }
}

// all three weights, single fp16 plane; blockIdx.y selects the array
__global__ __launch_bounds__(256) void prep_all(const float* __restrict__ w1,
                                                const float* __restrict__ w3,
                                                const float* __restrict__ w2) {
    const int which = blockIdx.y;
    const float* s = (which == 0) ? w1 : (which == 1) ? w3 : w2;
    __half* dh = (which == 0) ? g_W1 : (which == 1) ? g_W3 : g_W2;
    size_t i = ((size_t)blockIdx.x * 256 + threadIdx.x) * 4;
    float4 v = *(const float4*)(s + i);
    __half hbuf[4] = { __float2half_rn(v.x), __float2half_rn(v.y),
                       __float2half_rn(v.z), __float2half_rn(v.w) };
    *(uint2*)(dh + i) = *(uint2*)hbuf;
}

// router: warp per token, FP32 inputs (top-k selection is quantization-sensitive)
__global__ __launch_bounds__(256) void router_kernel(const float* __restrict__ gw) {
    __shared__ float sg[NE * CD];
    const int tid = threadIdx.x;
    for (int i = tid; i < NE * CD; i += 256) sg[i] = gw[i];
    __syncthreads();
    const int warp = tid >> 5, lane = tid & 31;
    const int t = blockIdx.x * 8 + warp;

    float acc[NE];
#pragma unroll
    for (int e = 0; e < NE; e++) acc[e] = 0.f;
    const float* xr = g_X + (size_t)t * CD;
    for (int c = lane; c < CD; c += 32) {
        float xv = xr[c];
#pragma unroll
        for (int e = 0; e < NE; e++) acc[e] = fmaf(xv, sg[e * CD + c], acc[e]);
    }
#pragma unroll
    for (int e = 0; e < NE; e++)
#pragma unroll
        for (int off = 16; off > 0; off >>= 1)
            acc[e] += __shfl_xor_sync(0xffffffffu, acc[e], off);

    if (lane == 0) {
        float mx = acc[0];
#pragma unroll
        for (int e = 1; e < NE; e++) mx = fmaxf(mx, acc[e]);
        float p[NE];
#pragma unroll
        for (int e = 0; e < NE; e++) p[e] = expf(acc[e] - mx);
        int i0 = 0; float b0 = p[0];
#pragma unroll
        for (int e = 1; e < NE; e++) if (p[e] > b0) { b0 = p[e]; i0 = e; }
        int i1 = (i0 == 0) ? 1 : 0; float b1 = p[i1];
#pragma unroll
        for (int e = 0; e < NE; e++)
            if (e != i0 && p[e] > b1) { b1 = p[e]; i1 = e; }
        float inv = 1.f / (b0 + b1);
        g_wt[t * 2 + 0] = b0 * inv;
        g_wt[t * 2 + 1] = b1 * inv;
        int p0 = atomicAdd(&g_cnt[i0], 1);
        g_list[i0 * TT + p0] = t * 2 + 0;
        int p1 = atomicAdd(&g_cnt[i1], 1);
        g_list[i1 * TT + p1] = t * 2 + 1;
    }
}

__global__ void schedule_kernel() {
    if (threadIdx.x == 0) {
        int nt = 0;
        for (int e = 0; e < NE; e++) {
            int c = g_cnt[e];
            for (int m0 = 0; m0 < c; m0 += 128) { g_tile_e[nt] = e; g_tile_m0[nt] = m0; nt++; }
        }
        g_ntiles = nt;
    }
}

// ---- tile loaders (cp.async), K-chunk 64, SW128 swizzled smem ----
// A: 128 rows x 8 q -> 1024 segs (4 iters)
__device__ __forceinline__ void load_A(uint32_t sbase, const __half* __restrict__ src0,
                                       int kstride, const int* asrc, int k0, int tid) {
#pragma unroll
    for (int i = 0; i < 4; i++) {
        int seg = tid + i * 256;          // 0..1023
        int row = seg >> 3, q = seg & 7;  // row 0..127, q 0..7
        const __half* src = src0 + (size_t)asrc[row] * kstride + k0 + q * 8;
        cp16(sbase + A_OFF + sw128((uint32_t)(row * 128 + q * 16)), src);
    }
}
// B gemm1: W1 (64r @0) + W3 (64r @8192) -> 1024 segs
__device__ __forceinline__ void load_B1(uint32_t sbase, int e, int n0, int k0, int tid) {
#pragma unroll
    for (int i = 0; i < 4; i++) {
        int seg = tid + i * 256;          // 0..1023
        int mat = seg >> 9;               // 0:W1 1:W3
        int rem = seg & 511;
        int row = rem >> 3, q = rem & 7;  // row 0..63
        const __half* base = mat ? g_W3 : g_W1;
        const __half* src = base + ((size_t)e * FD + n0 + row) * CD + k0 + q * 8;
        cp16(sbase + B_OFF + mat * 8192 + sw128((uint32_t)(row * 128 + q * 16)), src);
    }
}
// B gemm2: W2, 128 rows -> 1024 segs
__device__ __forceinline__ void load_B2(uint32_t sbase, int e, int n0, int k0, int tid) {
#pragma unroll
    for (int i = 0; i < 4; i++) {
        int seg = tid + i * 256;
        int row = (seg & 1023) >> 3, q = seg & 7;  // row 0..127
        const __half* src = g_W2 + ((size_t)e * CD + n0 + row) * FD + k0 + q * 8;
        cp16(sbase + B_OFF + sw128((uint32_t)(row * 128 + q * 16)), src);
    }
}

// ---- warp compute for one 64-k chunk: m32 x n64, single plane ----
__device__ __forceinline__ void chunk_mma(uint32_t sbase, int bOffBase, int bRowBase,
                                          int mb, int lane, float acc[2][8][4]) {
    const int arow = lane & 15, akoff = ((lane >> 4) & 1) * 8;
    const int brow = ((lane >> 4) & 1) * 8 + (lane & 7);
    const int bkoff = ((lane >> 3) & 1) * 8;
#pragma unroll
    for (int kb = 0; kb < 64; kb += 16) {
        uint32_t a[2][4];
#pragma unroll
        for (int mi = 0; mi < 2; mi++) {
            uint32_t off = sw128((uint32_t)((mb + mi * 16 + arow) * 128 + (kb + akoff) * 2));
            ldsm4(a[mi], sbase + A_OFF + off);
        }
        uint32_t bf[8][2];
#pragma unroll
        for (int n4 = 0; n4 < 4; n4++) {
            uint32_t off = sw128((uint32_t)((bRowBase + n4 * 16 + brow) * 128 + (kb + bkoff) * 2));
            uint32_t t[4];
            ldsm4(t, sbase + bOffBase + off);
            bf[2*n4][0]=t[0]; bf[2*n4][1]=t[1]; bf[2*n4+1][0]=t[2]; bf[2*n4+1][1]=t[3];
        }
#pragma unroll
        for (int mi = 0; mi < 2; mi++)
#pragma unroll
            for (int ni = 0; ni < 8; ni++)
                mma_f16(acc[mi][ni], a[mi], bf[ni]);
    }
}

// ------------------------------------------------------------------
// GEMM1: 128 rows x 64 ffn cols; warps 0-3 -> W1, warps 4-7 -> W3
__global__ __launch_bounds__(256, 2) void gemm1_mma() {
    if (blockIdx.y >= g_ntiles) return;
    extern __shared__ char dsm[];
    __shared__ int rows[128];
    __shared__ int asrc[128];

    const int tid = threadIdx.x, warp = tid >> 5, lane = tid & 31;
    const int e  = g_tile_e[blockIdx.y];
    const int m0 = g_tile_m0[blockIdx.y];
    const int ne = g_cnt[e];
    const int n0 = blockIdx.x * 64;

    if (tid < 128) {
        int i = m0 + tid;
        int ic = (i < ne) ? i : ne - 1;
        int entry = g_list[e * TT + ic];
        rows[tid] = (i < ne) ? entry : -1;
        asrc[tid] = entry >> 1;
    }
    __syncthreads();

    const uint32_t sb = smem_u32(dsm);
    const int mb = (warp & 3) * 32;
    const bool isW3 = warp >= 4;
    const int bOffBase = B_OFF + (isW3 ? 8192 : 0);

    float acc[2][8][4];
#pragma unroll
    for (int i = 0; i < 2; i++)
#pragma unroll
        for (int j = 0; j < 8; j++)
#pragma unroll
            for (int q = 0; q < 4; q++) acc[i][j][q] = 0.f;

#pragma unroll
    for (int pf = 0; pf < 2; pf++) {
        load_A(sb + pf * STG, g_Xf, CD, asrc, pf * 64, tid);
        load_B1(sb + pf * STG, e, n0, pf * 64, tid);
        CP_COMMIT();
    }
    for (int ch = 0; ch < 16; ch++) {
        PIPE_WAIT(ch);
        __syncthreads();
        if (ch + 2 < 16) {
            uint32_t nb = sb + ((ch + 2) % 3) * STG;
            load_A(nb, g_Xf, CD, asrc, (ch + 2) * 64, tid);
            load_B1(nb, e, n0, (ch + 2) * 64, tid);
            CP_COMMIT();
        }
        chunk_mma(sb + (ch % 3) * STG, bOffBase, 0, mb, lane, acc);
    }
    __syncthreads();

    // epilogue: exchange P1/P3 via smem, gelu*mul, store H fp16
    float* P1 = (float*)dsm;
    float* P3 = (float*)(dsm + 33792);
    float* myP = isW3 ? P3 : P1;
#pragma unroll
    for (int mi = 0; mi < 2; mi++)
#pragma unroll
        for (int ni = 0; ni < 8; ni++) {
            int m = mb + mi * 16 + (lane >> 2);
            int n = ni * 8 + (lane & 3) * 2;
            myP[m * 66 + n]       = acc[mi][ni][0];
            myP[m * 66 + n + 1]   = acc[mi][ni][1];
            myP[(m+8) * 66 + n]   = acc[mi][ni][2];
            myP[(m+8) * 66 + n+1] = acc[mi][ni][3];
        }
    __syncthreads();
    for (int idx = tid; idx < 128 * 64; idx += 256) {
        int m = idx >> 6, n = idx & 63;
        int entry = rows[m];
        if (entry < 0) continue;
        float d1 = P1[m * 66 + n];
        float d3 = P3[m * 66 + n];
        float gl = 0.5f * d1 * (1.f + erff(d1 * 0.70710678118654752f)) * d3;
        g_Hf[(size_t)entry * FD + n0 + n] = __float2half_rn(gl);
    }
}

// GEMM2: 128 rows x 128 out cols; warp grid 4(m) x 2(n)
__global__ __launch_bounds__(256, 2) void gemm2_mma() {
    if (blockIdx.y >= g_ntiles) return;
    extern __shared__ char dsm[];
    __shared__ int rows[128];
    __shared__ int asrc[128];
    __shared__ float wts[128];

    const int tid = threadIdx.x, warp = tid >> 5, lane = tid & 31;
    const int e  = g_tile_e[blockIdx.y];
    const int m0 = g_tile_m0[blockIdx.y];
    const int ne = g_cnt[e];
    const int n0 = blockIdx.x * 128;

    if (tid < 128) {
        int i = m0 + tid;
        int ic = (i < ne) ? i : ne - 1;
        int entry = g_list[e * TT + ic];
        rows[tid] = (i < ne) ? entry : -1;
        asrc[tid] = entry;
        wts[tid] = (i < ne) ? g_wt[entry] : 0.f;
    }
    __syncthreads();

    const uint32_t sb = smem_u32(dsm);
    const int mb = (warp >> 1) * 32;
    const int nb = (warp & 1) * 64;

    float acc[2][8][4];
#pragma unroll
    for (int i = 0; i < 2; i++)
#pragma unroll
        for (int j = 0; j < 8; j++)
#pragma unroll
            for (int q = 0; q < 4; q++) acc[i][j][q] = 0.f;

#pragma unroll
    for (int pf = 0; pf < 2; pf++) {
        load_A(sb + pf * STG, g_Hf, FD, asrc, pf * 64, tid);
        load_B2(sb + pf * STG, e, n0, pf * 64, tid);
        CP_COMMIT();
    }
    for (int ch = 0; ch < 16; ch++) {
        PIPE_WAIT(ch);
        __syncthreads();
        if (ch + 2 < 16) {
            uint32_t nbuf = sb + ((ch + 2) % 3) * STG;
            load_A(nbuf, g_Hf, FD, asrc, (ch + 2) * 64, tid);
            load_B2(nbuf, e, n0, (ch + 2) * 64, tid);
            CP_COMMIT();
        }
        chunk_mma(sb + (ch % 3) * STG, B_OFF, nb, mb, lane, acc);
    }

    // epilogue: scale by routing weight, store Y fp16
#pragma unroll
    for (int mi = 0; mi < 2; mi++) {
        int mB = mb + mi * 16 + (lane >> 2);
#pragma unroll
        for (int half = 0; half < 2; half++) {
            int m = mB + half * 8;
            int entry = rows[m];
            if (entry < 0) continue;
            float w = wts[m];
            __half* yr = g_Yf + (size_t)entry * CD + n0 + nb;
#pragma unroll
            for (int ni = 0; ni < 8; ni++) {
                int n = ni * 8 + (lane & 3) * 2;
                *(__half2*)(yr + n) = __floats2half2_rn(w * acc[mi][ni][half * 2],
                                                        w * acc[mi][ni][half * 2 + 1]);
            }
        }
    }
}

// sum two slots (fp16), transpose back to NCHW fp32
__global__ __launch_bounds__(256) void combine_out_kernel(float* __restrict__ out) {
    __shared__ float tile[32][33];
    const int b = blockIdx.z, c0 = blockIdx.y * 32, s0 = blockIdx.x * 32;
    const int tx = threadIdx.x, ty = threadIdx.y;
#pragma unroll
    for (int r = 0; r < 4; r++) {
        int ss = ty + r * 8;
        size_t t2 = (size_t)(b * HWD + s0 + ss) * 2;
        tile[ss][tx] = __half2float(g_Yf[t2 * CD + c0 + tx]) +
                       __half2float(g_Yf[(t2 + 1) * CD + c0 + tx]);
    }
    __syncthreads();
#pragma unroll
    for (int r = 0; r < 4; r++) {
        int cc = ty + r * 8;
        out[((size_t)(b * CD + c0 + cc)) * HWD + s0 + tx] = tile[tx][cc];
    }
}

// ------------------------------------------------------------------
extern "C" void kernel_launch(void* const* d_in, const int* in_sizes, int n_in,
                              void* d_out, int out_size) {
    const float* hs   = (const float*)d_in[0];
    const float* gate = (const float*)d_in[1];
    const float* w1   = (const float*)d_in[2];
    const float* w2   = (const float*)d_in[3];
    const float* w3   = (const float*)d_in[4];
    float* out = (float*)d_out;

    cudaFuncSetAttribute(gemm1_mma, cudaFuncAttributeMaxDynamicSharedMemorySize, DSM);
    cudaFuncSetAttribute(gemm2_mma, cudaFuncAttributeMaxDynamicSharedMemorySize, DSM);

    reset_kernel<<<1, 32>>>();
    transpose_pack_kernel<<<dim3(HWD / 32, CD / 32, BD), dim3(32, 8)>>>(hs);
    prep_all<<<dim3(NE * FD * CD / 4 / 256, 3), 256>>>(w1, w3, w2);
    router_kernel<<<TT / 8, 256>>>(gate);
    schedule_kernel<<<1, 32>>>();
    gemm1_mma<<<dim3(FD / 64, 136), 256, DSM>>>();
    gemm2_mma<<<dim3(CD / 128, 136), 256, DSM>>>();
    combine_out_kernel<<<dim3(HWD / 32, CD / 32, BD), dim3(32, 8)>>>(out);
}